// round 2
// baseline (speedup 1.0000x reference)
#include <cuda_runtime.h>
#include <cuda_bf16.h>

#define Bq 256
#define Tq 512
#define Kq 128
#define SOS 0
#define EOSI 1
#define NSM 152   // GB300 SM count; classic placement co-resides bid and bid+NSM

__device__ float g_E[Kq * Kq];   // exp(trans), row-major
__device__ int   g_perm[Bq];     // batch index sorted by descending length

// ---------------- prep: E = exp(trans) ----------------
__global__ void prep_E_kernel(const float* __restrict__ trans) {
    int i = blockIdx.x * blockDim.x + threadIdx.x;
    g_E[i] = expf(trans[i]);     // exp(-10000) -> 0 exactly, as desired
}

// ---------------- prep: lengths + rank permutation ----------------
__global__ void prep_perm_kernel(const float* __restrict__ mask) {
    __shared__ int slen[Bq];
    int tid = threadIdx.x, w = tid >> 5, lane = tid & 31;
    // 8 warps, coalesced row sums
    for (int r = w; r < Bq; r += 8) {
        float s = 0.f;
        const float* mr = mask + (size_t)r * Tq;
        for (int i = lane; i < Tq; i += 32) s += mr[i];
        #pragma unroll
        for (int o = 16; o > 0; o >>= 1) s += __shfl_xor_sync(0xffffffffu, s, o);
        if (lane == 0) slen[r] = (int)(s + 0.5f);
    }
    __syncthreads();
    // rank by descending length (O(B^2), trivial)
    int L = slen[tid];
    int rank = 0;
    for (int j = 0; j < Bq; j++) {
        int Lj = slen[j];
        rank += (Lj > L) || (Lj == L && j < tid);
    }
    g_perm[rank] = tid;
}

__device__ __forceinline__ unsigned long long pk2(float a, float b) {
    return (unsigned long long)__float_as_uint(a) |
           ((unsigned long long)__float_as_uint(b) << 32);
}

// ---------------- main CRF scan ----------------
__global__ void __launch_bounds__(128, 2) crf_main_kernel(
    const float* __restrict__ h, const float* __restrict__ mask,
    float* __restrict__ out)
{
    int bid = blockIdx.x;
    // Valid permutation of [0,256): bid<152 -> rank=bid (longest first);
    // bid in [152,256) -> rank = 255 - (bid-152), so the same-SM pair
    // (bid, bid+152) gets complementary ranks (i, 255-i): pair-sum ~ const.
    int rank = (bid < NSM) ? bid : (Bq - 1) - (bid - NSM);
    int b = g_perm[rank] & (Bq - 1);   // mask keeps any surprise in bounds
    int k = threadIdx.x;
    int lane = k & 31, w = k >> 5;

    __shared__ __align__(16) float p[Kq];
    __shared__ float wred[4];

    // thread k owns E row k in registers, packed for f32x2
    unsigned long long e2[Kq / 2];
    {
        const float4* er = reinterpret_cast<const float4*>(g_E + k * Kq);
        #pragma unroll
        for (int i = 0; i < Kq / 4; i++) {
            float4 f = er[i];
            e2[2 * i]     = pk2(f.x, f.y);
            e2[2 * i + 1] = pk2(f.z, f.w);
        }
    }

    // init: s = NEG except s[SOS]=0  ->  p[SOS]=1, others 0; C = 0
    p[k] = (k == SOS) ? 1.0f : 0.0f;
    float C = 0.0f;
    const float* hb = h + (size_t)b * Tq * Kq + k;
    const float* mb = mask + (size_t)b * Tq;
    float hcur = hb[0];
    float mcur = mb[0];
    __syncthreads();

    for (int t = 0; t < Tq; t++) {
        if (mcur == 0.0f) break;   // mask is a prefix of ones -> state frozen after
        float hnext = 0.f, mnext = 0.f;
        if (t + 1 < Tq) {          // prefetch next step's operands
            hnext = hb[(size_t)(t + 1) * Kq];
            mnext = mb[t + 1];
        }

        // dot[k] = sum_j E[k,j] * p[j]  via packed f32x2 FMA, 8 accumulators
        unsigned long long acc[8];
        #pragma unroll
        for (int i = 0; i < 8; i++) acc[i] = 0ull;

        const ulonglong2* pu = reinterpret_cast<const ulonglong2*>(p);
        #pragma unroll
        for (int i = 0; i < Kq / 4; i++) {
            ulonglong2 q = pu[i];   // broadcast LDS.128, conflict-free
            asm("fma.rn.f32x2 %0, %1, %2, %0;"
                : "+l"(acc[(2 * i) & 7]) : "l"(e2[2 * i]), "l"(q.x));
            asm("fma.rn.f32x2 %0, %1, %2, %0;"
                : "+l"(acc[(2 * i + 1) & 7]) : "l"(e2[2 * i + 1]), "l"(q.y));
        }
        float v = 0.f;
        #pragma unroll
        for (int i = 0; i < 8; i++)
            v += __uint_as_float((unsigned)acc[i]) +
                 __uint_as_float((unsigned)(acc[i] >> 32));

        v *= __expf(hcur);   // linear-domain emission

        // exact per-batch max for renormalization
        float wm = v;
        #pragma unroll
        for (int o = 16; o > 0; o >>= 1)
            wm = fmaxf(wm, __shfl_xor_sync(0xffffffffu, wm, o));
        if (lane == 0) wred[w] = wm;
        __syncthreads();
        float mx = fmaxf(fmaxf(wred[0], wred[1]), fmaxf(wred[2], wred[3]));

        p[k] = __fdividef(v, mx);
        C += __logf(mx);
        __syncthreads();

        hcur = hnext;
        mcur = mnext;
    }

    // out[b] = C + log( sum_k p[k] * exp(trans[EOS,k]) )
    float val = p[k] * g_E[EOSI * Kq + k];
    #pragma unroll
    for (int o = 16; o > 0; o >>= 1)
        val += __shfl_xor_sync(0xffffffffu, val, o);
    if (lane == 0) wred[w] = val;
    __syncthreads();
    if (k == 0)
        out[b] = C + __logf(wred[0] + wred[1] + wred[2] + wred[3]);
}

extern "C" void kernel_launch(void* const* d_in, const int* in_sizes, int n_in,
                              void* d_out, int out_size) {
    const float* h     = (const float*)d_in[0];
    const float* trans = (const float*)d_in[1];
    const float* mask  = (const float*)d_in[2];
    float* out = (float*)d_out;
    (void)in_sizes; (void)n_in; (void)out_size;

    prep_E_kernel<<<Kq, Kq>>>(trans);
    prep_perm_kernel<<<1, Bq>>>(mask);
    crf_main_kernel<<<Bq, Kq>>>(h, mask, out);
}

// round 3
// speedup vs baseline: 1.1626x; 1.1626x over previous
#include <cuda_runtime.h>
#include <cuda_bf16.h>

#define Bq 256
#define Tq 512
#define Kq 128
#define SOS 0
#define EOSI 1
#define NSM 152   // GB300 SM count; classic placement co-resides bid and bid+NSM

__device__ float g_E[Kq * Kq];   // exp(trans), row-major
__device__ int   g_perm[Bq];     // batch index sorted by descending length

// ---------------- prep: E = exp(trans)  AND  length-rank permutation ----------------
__global__ void prep_kernel(const float* __restrict__ trans,
                            const float* __restrict__ mask) {
    if (blockIdx.x < 64) {
        int i = blockIdx.x * 256 + threadIdx.x;
        g_E[i] = expf(trans[i]);          // exp(-10000) -> exactly 0
    } else {
        __shared__ int slen[Bq];
        int tid = threadIdx.x, w = tid >> 5, lane = tid & 31;
        for (int r = w; r < Bq; r += 8) {
            float s = 0.f;
            const float* mr = mask + (size_t)r * Tq;
            for (int i = lane; i < Tq; i += 32) s += mr[i];
            #pragma unroll
            for (int o = 16; o > 0; o >>= 1) s += __shfl_xor_sync(0xffffffffu, s, o);
            if (lane == 0) slen[r] = (int)(s + 0.5f);
        }
        __syncthreads();
        int L = slen[tid];
        int rank = 0;
        for (int j = 0; j < Bq; j++) {
            int Lj = slen[j];
            rank += (Lj > L) || (Lj == L && j < tid);
        }
        g_perm[rank] = tid;
    }
}

__device__ __forceinline__ unsigned long long pk2(float a, float b) {
    return (unsigned long long)__float_as_uint(a) |
           ((unsigned long long)__float_as_uint(b) << 32);
}
__device__ __forceinline__ void fma2(unsigned long long& d,
                                     unsigned long long a, unsigned long long b) {
    asm("fma.rn.f32x2 %0, %1, %2, %0;" : "+l"(d) : "l"(a), "l"(b));
}
__device__ __forceinline__ void add2(unsigned long long& d, unsigned long long a) {
    asm("add.rn.f32x2 %0, %0, %1;" : "+l"(d) : "l"(a));
}
__device__ __forceinline__ float warp_max_pos(float v) {
    unsigned u = __float_as_uint(v), r;
    asm("redux.sync.max.u32 %0, %1, 0xffffffff;" : "=r"(r) : "r"(u));
    return __uint_as_float(r);     // valid for non-negative floats
}

// ---------------- main CRF scan ----------------
__global__ void __launch_bounds__(128, 2) crf_main_kernel(
    const float* __restrict__ h, const float* __restrict__ mask,
    float* __restrict__ out)
{
    int bid = blockIdx.x;
    // same-SM pair (bid, bid+NSM) gets complementary length ranks (i, 255-i)
    int rank = (bid < NSM) ? bid : (Bq - 1) - (bid - NSM);
    int b = g_perm[rank] & (Bq - 1);
    int k = threadIdx.x;
    int lane = k & 31, w = k >> 5;

    __shared__ __align__(16) float pbuf[2][Kq];
    __shared__ float wred[2][4];

    // thread k owns E row k in registers, packed for f32x2
    unsigned long long e2[Kq / 2];
    {
        const float4* er = reinterpret_cast<const float4*>(g_E + k * Kq);
        #pragma unroll
        for (int i = 0; i < Kq / 4; i++) {
            float4 f = er[i];
            e2[2 * i]     = pk2(f.x, f.y);
            e2[2 * i + 1] = pk2(f.z, f.w);
        }
    }

    pbuf[0][k] = (k == SOS) ? 1.0f : 0.0f;   // p = exp(init - 0): 1 at SOS
    float C = 0.0f;          // applied log-offset
    float rinv = 1.0f;       // pending 1/mx (applied via eh next step)
    float pend = 0.0f;       // pending log(mx) (applied to C next step)

    const float* hb = h + (size_t)b * Tq * Kq + k;
    const float* mb = mask + (size_t)b * Tq;
    float eh   = __expf(hb[0]);
    float mcur = mb[0];
    __syncthreads();

    int t = 0;
    for (; t < Tq; t++) {
        if (mcur == 0.0f) break;             // prefix mask -> frozen afterwards

        // prefetch next step operands (off critical path)
        float hnext = 0.f, mnext = 0.f;
        if (t + 1 < Tq) { hnext = hb[(size_t)(t + 1) * Kq]; mnext = mb[t + 1]; }
        float ehnext = __expf(hnext);

        // apply deferred normalization from previous step
        eh *= rinv;
        C  += pend;

        // dot[k] = sum_j E[k,j] * p[j], packed f32x2, 8 accumulators
        unsigned long long acc[8];
        #pragma unroll
        for (int i = 0; i < 8; i++) acc[i] = 0ull;
        const ulonglong2* pu = reinterpret_cast<const ulonglong2*>(pbuf[t & 1]);
        #pragma unroll
        for (int i = 0; i < Kq / 4; i++) {
            ulonglong2 q = pu[i];            // broadcast LDS.128, conflict-free
            fma2(acc[(2 * i) & 7],     e2[2 * i],     q.x);
            fma2(acc[(2 * i + 1) & 7], e2[2 * i + 1], q.y);
        }
        // pairwise tree reduction of 8 packed accumulators
        add2(acc[0], acc[4]); add2(acc[1], acc[5]);
        add2(acc[2], acc[6]); add2(acc[3], acc[7]);
        add2(acc[0], acc[2]); add2(acc[1], acc[3]);
        add2(acc[0], acc[1]);
        float v = (__uint_as_float((unsigned)acc[0]) +
                   __uint_as_float((unsigned)(acc[0] >> 32))) * eh;

        pbuf[(t + 1) & 1][k] = v;            // write RAW (normalization deferred)

        // max reduction — result consumed only next step
        float wm = warp_max_pos(v);
        if (lane == 0) wred[t & 1][w] = wm;
        __syncthreads();                      // the ONLY barrier per step

        float mx = fmaxf(fmaxf(wred[t & 1][0], wred[t & 1][1]),
                         fmaxf(wred[t & 1][2], wred[t & 1][3]));
        rinv = 1.0f / mx;                     // off critical path
        pend = __logf(mx);

        eh = ehnext; mcur = mnext;
    }

    // out[b] = C + log( sum_k p_raw[k] * E[EOS,k] )   (last pend/rinv discarded)
    __syncthreads();
    float val = pbuf[t & 1][k] * g_E[EOSI * Kq + k];
    #pragma unroll
    for (int o = 16; o > 0; o >>= 1)
        val += __shfl_xor_sync(0xffffffffu, val, o);
    if (lane == 0) wred[0][w] = val;
    __syncthreads();
    if (k == 0)
        out[b] = C + __logf(wred[0][0] + wred[0][1] + wred[0][2] + wred[0][3]);
}

extern "C" void kernel_launch(void* const* d_in, const int* in_sizes, int n_in,
                              void* d_out, int out_size) {
    const float* h     = (const float*)d_in[0];
    const float* trans = (const float*)d_in[1];
    const float* mask  = (const float*)d_in[2];
    float* out = (float*)d_out;
    (void)in_sizes; (void)n_in; (void)out_size;

    prep_kernel<<<65, 256>>>(trans, mask);
    crf_main_kernel<<<Bq, Kq>>>(h, mask, out);
}